// round 2
// baseline (speedup 1.0000x reference)
#include <cuda_runtime.h>

// LSTM cell, fully fused fp32 GEMM + gate combine.
// gates[b, g, n] = sum_k combined[b,k] * W_g[k,n] + b_g[n],  combined = [x | h]
// new_cell = sig(gf)*c + sig(gi)*tanh(gc) ; new_hidden = sig(go)*tanh(new_cell)
//
// Tiling: each block computes a 64(B) x 64(H) output tile for ALL 4 gates.
// 256 threads, each owns a 4x4 microtile per gate (64 fp32 accumulators).

#define BM 64
#define BN 64
#define BK 32

__global__ __launch_bounds__(256, 2)
void lstm_fused_kernel(const float* __restrict__ x,
                       const float* __restrict__ h,
                       const float* __restrict__ cell,
                       const float* __restrict__ Wf, const float* __restrict__ bf,
                       const float* __restrict__ Wi, const float* __restrict__ bi,
                       const float* __restrict__ Wc, const float* __restrict__ bc,
                       const float* __restrict__ Wo, const float* __restrict__ bo,
                       float* __restrict__ outh, float* __restrict__ outc)
{
    __shared__ float As[BM][BK + 4];      // [m][k], +4 pad keeps float4 STS aligned, breaks bank conflicts
    __shared__ float Bs[4][BK][BN];       // [gate][k][n]

    const int tid = threadIdx.x;
    const int m0 = blockIdx.x * BM;
    const int n0 = blockIdx.y * BN;
    const int tx = tid & 15;              // n-direction (16)
    const int ty = tid >> 4;              // m-direction (16)

    const float* W[4] = {Wf, Wi, Wc, Wo};

    float acc[4][4][4];
    #pragma unroll
    for (int g = 0; g < 4; g++)
        #pragma unroll
        for (int j = 0; j < 4; j++)
            #pragma unroll
            for (int jj = 0; jj < 4; jj++) acc[g][j][jj] = 0.f;

    // A-tile load mapping: 64 rows x 32 k = 2048 floats = 2 float4/thread
    const int arow = tid >> 2;            // 0..63
    const int akq  = (tid & 3) * 8;       // 0,8,16,24 (float col)

    for (int k0 = 0; k0 < 2048; k0 += BK) {
        // combined = [x | h]: whole BK tile lives in exactly one source
        const float* Asrc;
        int kc;
        if (k0 < 1024) { Asrc = x; kc = k0; } else { Asrc = h; kc = k0 - 1024; }

        const float4* ap = reinterpret_cast<const float4*>(
            Asrc + (size_t)(m0 + arow) * 1024 + kc + akq);
        float4 a0 = ap[0];
        float4 a1 = ap[1];
        *reinterpret_cast<float4*>(&As[arow][akq])     = a0;
        *reinterpret_cast<float4*>(&As[arow][akq + 4]) = a1;

        // B tiles: per gate 32x64 = 2048 floats = 2 float4/thread
        #pragma unroll
        for (int g = 0; g < 4; g++) {
            #pragma unroll
            for (int i = 0; i < 2; i++) {
                int idx = tid + 256 * i;
                int kr = idx >> 4;          // 0..31
                int nq = (idx & 15) * 4;    // 0..60
                *reinterpret_cast<float4*>(&Bs[g][kr][nq]) =
                    *reinterpret_cast<const float4*>(
                        W[g] + (size_t)(k0 + kr) * 1024 + n0 + nq);
            }
        }
        __syncthreads();

        #pragma unroll
        for (int kk = 0; kk < BK; kk++) {
            float a[4];
            #pragma unroll
            for (int j = 0; j < 4; j++) a[j] = As[ty * 4 + j][kk];

            #pragma unroll
            for (int g = 0; g < 4; g++) {
                float4 b4 = *reinterpret_cast<const float4*>(&Bs[g][kk][tx * 4]);
                #pragma unroll
                for (int j = 0; j < 4; j++) {
                    acc[g][j][0] = fmaf(a[j], b4.x, acc[g][j][0]);
                    acc[g][j][1] = fmaf(a[j], b4.y, acc[g][j][1]);
                    acc[g][j][2] = fmaf(a[j], b4.z, acc[g][j][2]);
                    acc[g][j][3] = fmaf(a[j], b4.w, acc[g][j][3]);
                }
            }
        }
        __syncthreads();
    }

    // ---- fused LSTM epilogue ----
    float bias[4][4];
    #pragma unroll
    for (int jj = 0; jj < 4; jj++) {
        int n = n0 + tx * 4 + jj;
        bias[0][jj] = bf[n];
        bias[1][jj] = bi[n];
        bias[2][jj] = bc[n];
        bias[3][jj] = bo[n];
    }

    #pragma unroll
    for (int j = 0; j < 4; j++) {
        int m = m0 + ty * 4 + j;
        #pragma unroll
        for (int jj = 0; jj < 4; jj++) {
            int n = n0 + tx * 4 + jj;
            float gf = acc[0][j][jj] + bias[0][jj];
            float gi = acc[1][j][jj] + bias[1][jj];
            float gc = acc[2][j][jj] + bias[2][jj];
            float go = acc[3][j][jj] + bias[3][jj];

            float f = 1.f / (1.f + __expf(-gf));
            float i = 1.f / (1.f + __expf(-gi));
            float o = 1.f / (1.f + __expf(-go));
            float cd = tanhf(gc);

            float cold = cell[(size_t)m * 1024 + n];
            float nc = fmaf(f, cold, i * cd);
            float nh = o * tanhf(nc);

            outh[(size_t)m * 1024 + n] = nh;
            outc[(size_t)m * 1024 + n] = nc;
        }
    }
}

extern "C" void kernel_launch(void* const* d_in, const int* in_sizes, int n_in,
                              void* d_out, int out_size)
{
    const float* x    = (const float*)d_in[0];   // [B, 1024]
    const float* h    = (const float*)d_in[1];   // [B, 1024]
    const float* cell = (const float*)d_in[2];   // [B, 1024]
    const float* Wf   = (const float*)d_in[3];   // [2048, 1024]
    const float* bf   = (const float*)d_in[4];   // [1024]
    const float* Wi   = (const float*)d_in[5];
    const float* bi   = (const float*)d_in[6];
    const float* Wc   = (const float*)d_in[7];
    const float* bc   = (const float*)d_in[8];
    const float* Wo   = (const float*)d_in[9];
    const float* bo   = (const float*)d_in[10];

    const int I = 1024, H = 1024;
    const int B = in_sizes[0] / I;               // 8192

    float* outh = (float*)d_out;                 // new_hidden first
    float* outc = (float*)d_out + (size_t)B * H; // then new_cell

    dim3 grid(B / BM, H / BN);
    lstm_fused_kernel<<<grid, 256>>>(x, h, cell, Wf, bf, Wi, bi, Wc, bc, Wo, bo,
                                     outh, outc);
}

// round 4
// speedup vs baseline: 3.7146x; 3.7146x over previous
#include <cuda_runtime.h>
#include <cstdint>

// ============================================================================
// LSTM cell via mma.sync tf32 (family-portable PTX; tcgen05 unavailable
// because the harness targets compute_103 without the 'a' suffix).
//
// gates[m, g, n] = sum_k combined[m,k] * W_g[k,n],  combined = [x | h]
// CTA tile: M=128, per-gate N=64 (N_eff=256), BK=32, K=2048 (64 iters).
// 8 warps = 2(M) x 4(gate); warp tile 64(M) x 64(one gate).
// 3-stage cp.async pipeline. Epilogue: stage gates through smem, then
// fused sigmoid/tanh + cell update + coalesced STG.
// ============================================================================

#define SA        36                       // A smem row stride (floats)
#define SBF       72                       // B smem per-gate row stride (floats)
#define A_BYTES   (128 * SA * 4)           // 18432
#define BG_BYTES  (32 * SBF * 4)           // 9216
#define STAGE_BYTES (A_BYTES + 4 * BG_BYTES) // 55296
#define NSTAGES   3
#define SMEM_BYTES (NSTAGES * STAGE_BYTES)   // 165888
#define SS        260                      // staging row stride (floats)

__device__ __forceinline__ uint32_t s2u(const void* p) {
    uint32_t a;
    asm("{ .reg .u64 t; cvta.to.shared.u64 t, %1; cvt.u32.u64 %0, t; }"
        : "=r"(a) : "l"(p));
    return a;
}
__device__ __forceinline__ void cp16(uint32_t dst, const float* src) {
    asm volatile("cp.async.cg.shared.global [%0], [%1], 16;" :: "r"(dst), "l"(src));
}
#define CP_COMMIT() asm volatile("cp.async.commit_group;" ::: "memory")
#define CP_WAIT(n)  asm volatile("cp.async.wait_group %0;" :: "n"(n) : "memory")

__device__ __forceinline__ void ldsm4(uint32_t* r, uint32_t addr) {
    asm volatile("ldmatrix.sync.aligned.m8n8.x4.shared.b16 {%0,%1,%2,%3}, [%4];"
                 : "=r"(r[0]), "=r"(r[1]), "=r"(r[2]), "=r"(r[3]) : "r"(addr));
}
__device__ __forceinline__ uint32_t f2tf(uint32_t bits) {
    float f = __uint_as_float(bits);
    uint32_t r;
    asm("cvt.rna.tf32.f32 %0, %1;" : "=r"(r) : "f"(f));
    return r;
}
__device__ __forceinline__ void mma8(float* d, const uint32_t* a, const uint32_t* b) {
    asm volatile(
        "mma.sync.aligned.m16n8k8.row.col.f32.tf32.tf32.f32 "
        "{%0,%1,%2,%3}, {%4,%5,%6,%7}, {%8,%9}, {%0,%1,%2,%3};"
        : "+f"(d[0]), "+f"(d[1]), "+f"(d[2]), "+f"(d[3])
        : "r"(a[0]), "r"(a[1]), "r"(a[2]), "r"(a[3]), "r"(b[0]), "r"(b[1]));
}

__device__ __forceinline__ float sigf(float v) {
    return __fdividef(1.0f, 1.0f + __expf(-v));
}
__device__ __forceinline__ float tanhf_e(float v) {
    float ax = fabsf(v);
    float e = __expf(-2.0f * ax);
    float t = __fdividef(1.0f - e, 1.0f + e);
    return copysignf(t, v);
}

__device__ __forceinline__ void load_stage(
    int T, uint32_t sb, int tid, int m0, int n0,
    const float* __restrict__ x, const float* __restrict__ h,
    const float* __restrict__ Wf, const float* __restrict__ Wi,
    const float* __restrict__ Wc, const float* __restrict__ Wo)
{
    const int s = T % NSTAGES;
    const uint32_t Ab = sb + s * STAGE_BYTES;
    const int k0 = T * 32;
    const float* Asrc = (k0 < 1024) ? x : h;
    const int kc = (k0 < 1024) ? k0 : k0 - 1024;

    // A tile: 128 rows x 32 floats (128B/row) = 1024 x 16B chunks
    #pragma unroll
    for (int c = 0; c < 4; c++) {
        int ci = c * 256 + tid;
        int row = ci >> 3, col = ci & 7;
        cp16(Ab + row * (SA * 4) + col * 16,
             Asrc + (size_t)(m0 + row) * 1024 + kc + col * 4);
    }
    // B tiles: 4 gates x 32 k-rows x 64 floats = 2048 x 16B chunks
    const uint32_t Bb = Ab + A_BYTES;
    #pragma unroll
    for (int c = 0; c < 8; c++) {
        int ci = c * 256 + tid;
        int g = ci >> 9;                 // constant per unrolled c
        int rem = ci & 511;
        int kr = rem >> 4, col = rem & 15;
        const float* Wg = (g == 0) ? Wf : (g == 1) ? Wi : (g == 2) ? Wc : Wo;
        cp16(Bb + g * BG_BYTES + kr * (SBF * 4) + col * 16,
             Wg + (size_t)(k0 + kr) * 1024 + n0 + col * 4);
    }
}

__global__ void __launch_bounds__(256, 1)
lstm_mma(const float* __restrict__ x, const float* __restrict__ h,
         const float* __restrict__ cellp,
         const float* __restrict__ Wf, const float* __restrict__ bf,
         const float* __restrict__ Wi, const float* __restrict__ bi,
         const float* __restrict__ Wc, const float* __restrict__ bc,
         const float* __restrict__ Wo, const float* __restrict__ bo,
         float* __restrict__ outh, float* __restrict__ outc)
{
    extern __shared__ float sm[];
    const uint32_t sb = s2u(sm);

    const int tid  = threadIdx.x;
    const int lane = tid & 31;
    const int wid  = tid >> 5;
    const int g    = wid & 3;             // gate handled by this warp
    const int wm   = wid >> 2;            // M half (0/1)
    const int m0   = blockIdx.x * 128;
    const int n0   = blockIdx.y * 64;

    // ldmatrix lane address pieces (A frags)
    const int lr   = lane & 7;
    const int sel  = lane >> 3;
    const int arow = (sel & 1) * 8 + lr;      // row offset within m16 tile
    const int acolB = (sel >> 1) * 16;        // byte offset within k8 (0 or 16)
    // B frag lane pieces
    const int kq = lane & 3;
    const int nq = lane >> 2;

    float acc[4][8][4];
    #pragma unroll
    for (int mt = 0; mt < 4; mt++)
        #pragma unroll
        for (int nt = 0; nt < 8; nt++)
            #pragma unroll
            for (int j = 0; j < 4; j++) acc[mt][nt][j] = 0.0f;

    load_stage(0, sb, tid, m0, n0, x, h, Wf, Wi, Wc, Wo); CP_COMMIT();
    load_stage(1, sb, tid, m0, n0, x, h, Wf, Wi, Wc, Wo); CP_COMMIT();

    for (int t = 0; t < 64; t++) {
        if (t < 62) {
            load_stage(t + 2, sb, tid, m0, n0, x, h, Wf, Wi, Wc, Wo);
            CP_COMMIT();
            CP_WAIT(2);
        } else if (t == 62) {
            CP_WAIT(1);
        } else {
            CP_WAIT(0);
        }
        __syncthreads();

        const uint32_t Ab = sb + (t % NSTAGES) * STAGE_BYTES;
        const uint32_t Bg = Ab + A_BYTES + g * BG_BYTES;

        #pragma unroll
        for (int ks = 0; ks < 4; ks++) {
            uint32_t a[4][4];
            #pragma unroll
            for (int mt = 0; mt < 4; mt++) {
                uint32_t ad = Ab + (uint32_t)(wm * 64 + mt * 16 + arow) * (SA * 4)
                                 + (uint32_t)(ks * 32 + acolB);
                ldsm4(a[mt], ad);
            }
            uint32_t b[8][2];
            #pragma unroll
            for (int nt = 0; nt < 8; nt++) {
                uint32_t bd = Bg + (uint32_t)(ks * 8 + kq) * (SBF * 4)
                                 + (uint32_t)(nt * 8 + nq) * 4;
                asm volatile("ld.shared.b32 %0, [%1];" : "=r"(b[nt][0]) : "r"(bd));
                asm volatile("ld.shared.b32 %0, [%1];" : "=r"(b[nt][1]) : "r"(bd + 4 * SBF * 4));
            }
            #pragma unroll
            for (int mt = 0; mt < 4; mt++)
                #pragma unroll
                for (int j = 0; j < 4; j++) a[mt][j] = f2tf(a[mt][j]);
            #pragma unroll
            for (int nt = 0; nt < 8; nt++) {
                b[nt][0] = f2tf(b[nt][0]);
                b[nt][1] = f2tf(b[nt][1]);
            }
            #pragma unroll
            for (int mt = 0; mt < 4; mt++)
                #pragma unroll
                for (int nt = 0; nt < 8; nt++)
                    mma8(acc[mt][nt], a[mt], b[nt]);
        }
        __syncthreads();
    }

    // ---- stage gate values through smem (gates live in different warps) ----
    #pragma unroll
    for (int mt = 0; mt < 4; mt++) {
        #pragma unroll
        for (int nt = 0; nt < 8; nt++) {
            int r0 = wm * 64 + mt * 16 + (lane >> 2);
            int cb = g * 64 + nt * 8 + (lane & 3) * 2;
            *(float2*)&sm[(size_t)r0 * SS + cb]       = make_float2(acc[mt][nt][0], acc[mt][nt][1]);
            *(float2*)&sm[(size_t)(r0 + 8) * SS + cb] = make_float2(acc[mt][nt][2], acc[mt][nt][3]);
        }
    }
    __syncthreads();

    // ---- fused LSTM combine + store ----
    const int nl = tid & 63;
    const int n  = n0 + nl;
    const float Bf = __ldg(bf + n);
    const float Bi = __ldg(bi + n);
    const float Bc = __ldg(bc + n);
    const float Bo = __ldg(bo + n);

    #pragma unroll 4
    for (int r = 0; r < 32; r++) {
        int m = r * 4 + (tid >> 6);
        const float* row = &sm[(size_t)m * SS];
        float gf = row[nl]       + Bf;
        float gi = row[64 + nl]  + Bi;
        float gc = row[128 + nl] + Bc;
        float go = row[192 + nl] + Bo;

        float F  = sigf(gf);
        float I  = sigf(gi);
        float O  = sigf(go);
        float CD = tanhf_e(gc);

        size_t gidx = (size_t)(m0 + m) * 1024 + n;
        float cold = __ldg(cellp + gidx);
        float nc = fmaf(F, cold, I * CD);
        float nh = O * tanhf_e(nc);
        outh[gidx] = nh;
        outc[gidx] = nc;
    }
}

extern "C" void kernel_launch(void* const* d_in, const int* in_sizes, int n_in,
                              void* d_out, int out_size)
{
    const float* x    = (const float*)d_in[0];   // [B, 1024]
    const float* h    = (const float*)d_in[1];   // [B, 1024]
    const float* cell = (const float*)d_in[2];   // [B, 1024]
    const float* Wf   = (const float*)d_in[3];   // [2048, 1024]
    const float* bf   = (const float*)d_in[4];
    const float* Wi   = (const float*)d_in[5];
    const float* bi   = (const float*)d_in[6];
    const float* Wc   = (const float*)d_in[7];
    const float* bc   = (const float*)d_in[8];
    const float* Wo   = (const float*)d_in[9];
    const float* bo   = (const float*)d_in[10];

    const int B = in_sizes[0] / 1024;            // 8192

    static bool attr_set = false;
    if (!attr_set) {
        cudaFuncSetAttribute(lstm_mma, cudaFuncAttributeMaxDynamicSharedMemorySize,
                             SMEM_BYTES);
        attr_set = true;
    }

    float* outh = (float*)d_out;
    float* outc = (float*)d_out + (size_t)B * 1024;

    dim3 grid(B / 128, 16);
    lstm_mma<<<grid, 256, SMEM_BYTES>>>(x, h, cell, Wf, bf, Wi, bi, Wc, bc,
                                        Wo, bo, outh, outc);
}